// round 9
// baseline (speedup 1.0000x reference)
#include <cuda_runtime.h>

// Problem geometry: N = (262144, 65536, 16384), final block rank R = 21
#define NI 16384
#define A_ELEMS (21 * 21 * NI)
#define LOGDET_IDX (2 * A_ELEMS)
#define ZOUT_OFF (LOGDET_IDX + 1)   // odd float offset -> scalar stores only
#define ZOUT_PLANE (21 * NI)
#define TILE_I 32
#define NBLK (NI / TILE_I)          // 512
#define NTHREADS 224                // 7 warps, 3 rows each

struct Cpx { float re, im; };

__device__ __forceinline__ Cpx cmul(Cpx a, Cpx b) {
    Cpx r; r.re = a.re * b.re - a.im * b.im; r.im = a.re * b.im + a.im * b.re; return r;
}
// a * conj(b)
__device__ __forceinline__ Cpx cmulc(Cpx a, Cpx b) {
    Cpx r; r.re = a.re * b.re + a.im * b.im; r.im = a.im * b.re - a.re * b.im; return r;
}
__device__ __forceinline__ Cpx cinv(Cpx a) {
    float d = 1.0f / (a.re * a.re + a.im * a.im);
    Cpx r; r.re = a.re * d; r.im = -a.im * d; return r;
}

__device__ double g_ld[NBLK];
__device__ unsigned int g_count = 0;

__global__ void __launch_bounds__(NTHREADS, 5) kmain(
    const float* __restrict__ l00r, const float* __restrict__ l00i,
    const float* __restrict__ l01r, const float* __restrict__ l01i,
    const float* __restrict__ l02r, const float* __restrict__ l02i,
    const float* __restrict__ l11r, const float* __restrict__ l11i,
    const float* __restrict__ l12r, const float* __restrict__ l12i,
    const float* __restrict__ l22r, const float* __restrict__ l22i,
    const float* __restrict__ zre,  const float* __restrict__ zim,
    float* __restrict__ out)
{
    __shared__ float2 shT2[20 * 32];        // level-2 T vector
    __shared__ float2 shZ[21 * 32];         // z per plane
    __shared__ float2 shL1[4 * 13 * 32];    // per s: P1[0..3], T1[4..7]=T1, 8..11=a0, 12=invS1
    __shared__ float2 shM2[4 * 32];
    __shared__ float2 shInvS2[32];
    __shared__ float2 shW[32];              // W = sum_{k<20} conj(T2k) z[k] - z[20]
    __shared__ float2 shV[4 * 32];          // V_s
    __shared__ float2 shU[4 * 32];          // U_s
    __shared__ float  shLd[5];
    __shared__ int    shLast;

    const int lane = threadIdx.x & 31;
    const int warp = threadIdx.x >> 5;
    const int i = blockIdx.x * TILE_I + lane;

    float facc = 0.f;
    float pre22r = 0.f, pre22i = 0.f;

    // registers persisting for phase 1b (warps 0-3)
    Cpx rT1[4], rP1[4];

    if (warp < 4) {
        // ---- Phase 1: s = warp ----
        const int s = warp;
        const int m = s * NI + i;

        Cpx a0[4];
        Cpx M1; M1.re = 0.f; M1.im = 0.f;
        #pragma unroll
        for (int jj = 0; jj < 4; jj++) {
            const int idx = (jj * 4 + s) * NI + i;
            Cpx l00; l00.re = l00r[idx]; l00.im = l00i[idx];
            Cpx l01; l01.re = l01r[idx]; l01.im = l01i[idx];
            a0[jj] = cinv(l00);
            rT1[jj] = cmul(l01, a0[jj]);
            Cpx t = cmulc(rT1[jj], l01);
            M1.re += t.re; M1.im += t.im;
            facc += 0.5f * __logf(l00.re * l00.re + l00.im * l00.im);
        }
        Cpx S1; S1.re = l11r[m] - M1.re; S1.im = l11i[m] - M1.im;
        facc += 0.5f * __logf(S1.re * S1.re + S1.im * S1.im);
        const Cpx invS1 = cinv(S1);

        Cpx b[5];
        #pragma unroll
        for (int p = 0; p < 4; p++) {
            const int idx = (p * 4 + s) * NI + i;
            b[p].re = l02r[idx]; b[p].im = l02i[idx];
        }
        b[4].re = l12r[m]; b[4].im = l12i[m];

        Cpx w; w.re = 0.f; w.im = 0.f;
        #pragma unroll
        for (int p = 0; p < 4; p++) {
            Cpx t = cmulc(b[p], rT1[p]);
            w.re += t.re; w.im += t.im;
        }
        Cpx wm; wm.re = w.re - b[4].re; wm.im = w.im - b[4].im;

        Cpx t2b = cmul(invS1, b[4]);
        Cpx M2; M2.re = 0.f; M2.im = 0.f;
        #pragma unroll
        for (int q = 0; q < 4; q++) {
            rP1[q] = cmul(rT1[q], invS1);
            Cpx t2 = cmul(rP1[q], wm);
            Cpx t = cmul(a0[q], b[q]);
            t2.re += t.re; t2.im += t.im;
            shT2[(q * 4 + s) * 32 + lane] = make_float2(t2.re, t2.im);
            Cpx mm = cmulc(t2, b[q]);
            M2.re += mm.re; M2.im += mm.im;
            Cpx u = cmulc(b[q], rP1[q]);
            t2b.re -= u.re; t2b.im -= u.im;
        }
        shT2[(16 + s) * 32 + lane] = make_float2(t2b.re, t2b.im);
        Cpx mm = cmulc(t2b, b[4]);
        M2.re += mm.re; M2.im += mm.im;
        shM2[s * 32 + lane] = make_float2(M2.re, M2.im);

        // compact level-1 state
        #pragma unroll
        for (int q = 0; q < 4; q++) {
            shL1[(s * 13 + q) * 32 + lane]     = make_float2(rP1[q].re, rP1[q].im);
            shL1[(s * 13 + 4 + q) * 32 + lane] = make_float2(rT1[q].re, rT1[q].im);
            shL1[(s * 13 + 8 + q) * 32 + lane] = make_float2(a0[q].re, a0[q].im);
        }
        shL1[(s * 13 + 12) * 32 + lane] = make_float2(invS1.re, invS1.im);
    } else {
        // ---- z staging: warps 4..6 load 7 planes each ----
        if (warp == 4) { pre22r = l22r[i]; pre22i = l22i[i]; }
        const int pbase = (warp - 4) * 7;
        #pragma unroll
        for (int t = 0; t < 7; t++) {
            const int pl = pbase + t;
            shZ[pl * 32 + lane] = make_float2(zre[pl * NI + i], zim[pl * NI + i]);
        }
    }
    __syncthreads();

    // ---- Phase 1b ----
    if (warp < 4) {
        // V_s = sum_q z[q4+s] conj(T1q);  U_s = sum_q z[q4+s] conj(P1q)
        const int s = warp;
        Cpx V; V.re = 0.f; V.im = 0.f;
        Cpx U; U.re = 0.f; U.im = 0.f;
        #pragma unroll
        for (int q = 0; q < 4; q++) {
            float2 zv = shZ[(q * 4 + s) * 32 + lane];
            Cpx z; z.re = zv.x; z.im = zv.y;
            Cpx tv = cmulc(z, rT1[q]);
            V.re += tv.re; V.im += tv.im;
            Cpx tu = cmulc(z, rP1[q]);
            U.re += tu.re; U.im += tu.im;
        }
        shV[s * 32 + lane] = make_float2(V.re, V.im);
        shU[s * 32 + lane] = make_float2(U.re, U.im);
    } else if (warp == 4) {
        float2 m0 = shM2[0 * 32 + lane], m1 = shM2[1 * 32 + lane],
               m2 = shM2[2 * 32 + lane], m3 = shM2[3 * 32 + lane];
        Cpx S2; S2.re = pre22r - (m0.x + m1.x + m2.x + m3.x);
                S2.im = pre22i - (m0.y + m1.y + m2.y + m3.y);
        facc = 0.5f * __logf(S2.re * S2.re + S2.im * S2.im);
        Cpx inv = cinv(S2);
        shInvS2[lane] = make_float2(inv.re, inv.im);
    } else if (warp == 5) {
        // W = sum_{k<20} z[k] conj(T2k) - z[20]
        Cpx W; W.re = 0.f; W.im = 0.f;
        #pragma unroll
        for (int k = 0; k < 20; k++) {
            float2 tv = shT2[k * 32 + lane];
            float2 zv = shZ[k * 32 + lane];
            Cpx T; T.re = tv.x; T.im = tv.y;
            Cpx z; z.re = zv.x; z.im = zv.y;
            Cpx t = cmulc(z, T);
            W.re += t.re; W.im += t.im;
        }
        float2 z20 = shZ[20 * 32 + lane];
        W.re -= z20.x; W.im -= z20.y;
        shW[lane] = make_float2(W.re, W.im);
    }
    if (warp < 5) {
        #pragma unroll
        for (int off = 16; off > 0; off >>= 1)
            facc += __shfl_down_sync(0xffffffffu, facc, off);
        if (lane == 0) shLd[warp] = facc;
    }
    __syncthreads();

    // ---- Phase 2: warp w owns rows w, w+7, w+14 ----
    float2 iv = shInvS2[lane];
    Cpx invS2; invS2.re = iv.x; invS2.im = iv.y;
    float2 wv = shW[lane];
    Cpx W; W.re = wv.x; W.im = wv.y;

    Cpx P2[3], P1p[3], a0p[3], iS1[3];
    int sr[3], pr[3];
    bool isB2[3];
    float *oR[3], *oI[3];
    Cpx zo[3];

    #pragma unroll
    for (int r = 0; r < 3; r++) {
        const int j = warp + 7 * r;
        sr[r] = j & 3; pr[r] = j >> 2; isB2[r] = (j == 20);
        oR[r] = out + (size_t)(j * 21) * NI + i;
        oI[r] = out + A_ELEMS + (size_t)(j * 21) * NI + i;
        P2[r].re = P2[r].im = 0.f;
        P1p[r].re = P1p[r].im = 0.f;
        a0p[r].re = a0p[r].im = 0.f;
        iS1[r].re = iS1[r].im = 0.f;
        if (isB2[r]) {
            // zout[20] = -conj(invS2) (W + z20) + z20 invS2
            float2 z20v = shZ[20 * 32 + lane];
            Cpx z20; z20.re = z20v.x; z20.im = z20v.y;
            Cpx Wp; Wp.re = W.re + z20.re; Wp.im = W.im + z20.im;
            Cpx cs; cs.re = -invS2.re; cs.im = invS2.im;   // -conj(invS2)
            Cpx t = cmul(cs, Wp);
            Cpx u = cmul(z20, invS2);
            zo[r].re = t.re + u.re; zo[r].im = t.im + u.im;
        } else {
            float2 t = shT2[j * 32 + lane];
            Cpx T2j; T2j.re = t.x; T2j.im = t.y;
            P2[r] = cmul(T2j, invS2);
            // zout = P2j * W + A1 part
            zo[r] = cmul(P2[r], W);
            float2 z16v = shZ[(16 + sr[r]) * 32 + lane];
            Cpx z16; z16.re = z16v.x; z16.im = z16v.y;
            if (pr[r] == 4) {
                float2 v = shL1[(sr[r] * 13 + 12) * 32 + lane];
                iS1[r].re = v.x; iS1[r].im = v.y;
                float2 uv = shU[sr[r] * 32 + lane];
                Cpx t1 = cmul(z16, iS1[r]);
                zo[r].re += t1.re - uv.x; zo[r].im += t1.im - uv.y;
            } else {
                float2 a = shL1[(sr[r] * 13 + pr[r]) * 32 + lane];
                P1p[r].re = a.x; P1p[r].im = a.y;
                float2 c = shL1[(sr[r] * 13 + 8 + pr[r]) * 32 + lane];
                a0p[r].re = c.x; a0p[r].im = c.y;
                float2 vv = shV[sr[r] * 32 + lane];
                Cpx vm; vm.re = vv.x - z16.re; vm.im = vv.y - z16.im;
                Cpx t1 = cmul(P1p[r], vm);
                float2 zpv = shZ[(pr[r] * 4 + sr[r]) * 32 + lane];
                Cpx zp; zp.re = zpv.x; zp.im = zpv.y;
                Cpx t2 = cmul(zp, a0p[r]);
                zo[r].re += t1.re + t2.re; zo[r].im += t1.im + t2.im;
            }
        }
    }

    #pragma unroll
    for (int k = 0; k < 20; k++) {
        float2 tv = shT2[k * 32 + lane];
        Cpx Tk; Tk.re = tv.x; Tk.im = tv.y;
        #pragma unroll
        for (int r = 0; r < 3; r++) {
            Cpx v;
            if (isB2[r]) {
                Cpx P = cmul(Tk, invS2);
                v.re = -P.re; v.im = P.im;                 // -conj(P2[k])
            } else {
                v = cmulc(P2[r], Tk);
                if ((k & 3) == sr[r]) {                    // warp-uniform A1 hit
                    const int q = k >> 2;
                    if (pr[r] == 4) {
                        if (q == 4) { v.re += iS1[r].re; v.im += iS1[r].im; }
                        else {
                            float2 p1q = shL1[(sr[r] * 13 + q) * 32 + lane];
                            v.re -= p1q.x; v.im += p1q.y;  // -conj(P1[q])
                        }
                    } else {
                        if (q == 4) { v.re -= P1p[r].re; v.im -= P1p[r].im; }
                        else {
                            float2 t1 = shL1[(sr[r] * 13 + 4 + q) * 32 + lane];
                            Cpx T1q; T1q.re = t1.x; T1q.im = t1.y;
                            Cpx tt = cmulc(P1p[r], T1q);
                            v.re += tt.re; v.im += tt.im;
                            if (q == pr[r]) { v.re += a0p[r].re; v.im += a0p[r].im; }
                        }
                    }
                }
            }
            oR[r][(size_t)k * NI] = v.re;
            oI[r][(size_t)k * NI] = v.im;
        }
    }
    // column k = 20
    #pragma unroll
    for (int r = 0; r < 3; r++) {
        Cpx v;
        if (isB2[r]) v = invS2;
        else { v.re = -P2[r].re; v.im = -P2[r].im; }
        oR[r][(size_t)20 * NI] = v.re;
        oI[r][(size_t)20 * NI] = v.im;
    }
    // zout (ZOUT_OFF odd -> scalar stores)
    #pragma unroll
    for (int r = 0; r < 3; r++) {
        const int j = warp + 7 * r;
        out[ZOUT_OFF + (size_t)j * NI + i] = zo[r].re;
        out[ZOUT_OFF + ZOUT_PLANE + (size_t)j * NI + i] = zo[r].im;
    }

    // ---- logdet: per-block partial, last block finalizes ----
    if (threadIdx.x == 0) {
        double p = (double)(shLd[0] + shLd[1] + shLd[2] + shLd[3] + shLd[4]);
        g_ld[blockIdx.x] = p;
        __threadfence();
        unsigned int v = atomicAdd(&g_count, 1u);
        shLast = (v == NBLK - 1) ? 1 : 0;
    }
    __syncthreads();
    if (shLast && warp == 0) {
        __threadfence();
        double a = 0.0;
        #pragma unroll
        for (int q = 0; q < NBLK / 32; q++)
            a += g_ld[q * 32 + lane];
        #pragma unroll
        for (int off = 16; off > 0; off >>= 1)
            a += __shfl_xor_sync(0xffffffffu, a, off);
        if (lane == 0) {
            out[LOGDET_IDX] = (float)a;
            g_count = 0;   // reset for graph replay
        }
    }
}

extern "C" void kernel_launch(void* const* d_in, const int* in_sizes, int n_in,
                              void* d_out, int out_size)
{
    const float* l00r = (const float*)d_in[0];
    const float* l00i = (const float*)d_in[1];
    const float* l01r = (const float*)d_in[2];
    const float* l01i = (const float*)d_in[3];
    const float* l02r = (const float*)d_in[4];
    const float* l02i = (const float*)d_in[5];
    const float* l11r = (const float*)d_in[6];
    const float* l11i = (const float*)d_in[7];
    const float* l12r = (const float*)d_in[8];
    const float* l12i = (const float*)d_in[9];
    const float* l22r = (const float*)d_in[10];
    const float* l22i = (const float*)d_in[11];
    const float* zre  = (const float*)d_in[12];
    const float* zim  = (const float*)d_in[13];
    float* out = (float*)d_out;

    kmain<<<NBLK, NTHREADS>>>(l00r, l00i, l01r, l01i, l02r, l02i,
                              l11r, l11i, l12r, l12i, l22r, l22i,
                              zre, zim, out);
}